// round 2
// baseline (speedup 1.0000x reference)
#include <cuda_runtime.h>
#include <cstdint>

// ---------------------------------------------------------------------------
// Problem constants
// ---------------------------------------------------------------------------
#define NG    512           // graphs
#define NPG   116           // nodes per graph
#define EMB   300
#define NODES (NG * NPG)    // 59392
#define ADJ_ELEMS (NG * NPG * NPG)   // 6,889,472
#define NLAYER 5
#define BN_EPS 1e-5f

#define STAT_BLOCKS 232     // 232 * 256 = 59392 rows exactly

// GEMM tiling
#define BM 64
#define BN 64
#define BK 16

// ---------------------------------------------------------------------------
// Device scratch (static allocation only; no cudaMalloc allowed)
// ---------------------------------------------------------------------------
__device__ float g_A[ADJ_ELEMS];                 // dense adjacency  [G][116][116]
__device__ float g_Z[(size_t)NODES * EMB];       // post-aggregation
__device__ float g_T[(size_t)NODES * EMB];       // hidden (after relu(W1))
__device__ float g_H[(size_t)NODES * EMB];       // layer output / BN in-place
__device__ float g_part[STAT_BLOCKS * 600];      // BN partial sums  [blk][sum300|sq300]
__device__ float g_ss[600];                      // BN scale[300], shift[300]

// ---------------------------------------------------------------------------
// Adjacency construction
// ---------------------------------------------------------------------------
__global__ void zero4_kernel(float4* __restrict__ p, int n4) {
    int i = blockIdx.x * blockDim.x + threadIdx.x;
    if (i < n4) p[i] = make_float4(0.f, 0.f, 0.f, 0.f);
}

__global__ void build_adj_kernel(const int* __restrict__ ei,
                                 const float* __restrict__ ew,
                                 const float* __restrict__ bern,
                                 int E) {
    int e = blockIdx.x * blockDim.x + threadIdx.x;
    if (e >= E) return;
    int r = ei[e];
    int c = ei[E + e];
    int g = r / NPG;
    float w = ew[e] * bern[e];
    g_A[(size_t)g * (NPG * NPG) + (r - g * NPG) * NPG + (c - g * NPG)] = w;
}

// ---------------------------------------------------------------------------
// MLP GEMM:  C[M,N] = act( X[M,K] @ W[K,N] + bias[N] )
// 64x64x16 tiles, 4x4 register microtile, 256 threads
// ---------------------------------------------------------------------------
__global__ void __launch_bounds__(256)
gemm_bias_act(const float* __restrict__ X, const float* __restrict__ W,
              const float* __restrict__ bias, float* __restrict__ C,
              int M, int K, int N, int relu) {
    __shared__ float As[BK][BM + 4];   // transposed: As[k][m]
    __shared__ float Bs[BK][BN + 4];

    const int tid  = threadIdx.x;
    const int m0   = blockIdx.x * BM;
    const int n0   = blockIdx.y * BN;
    const int arow = tid >> 2;             // 0..63 (m within tile)
    const int acol = (tid & 3) << 2;       // 0,4,8,12 (k within tile)
    const int brow = tid >> 4;             // 0..15 (k within tile)
    const int bcol = (tid & 15) << 2;      // 0..60 (n within tile)
    const int tx   = tid & 15;
    const int ty   = tid >> 4;

    float acc[4][4] = {};

    for (int k0 = 0; k0 < K; k0 += BK) {
        // --- load X tile (transposed into As) ---
        float4 av = make_float4(0.f, 0.f, 0.f, 0.f);
        {
            int m = m0 + arow;
            if (m < M) {
                const float* src = X + (size_t)m * K + k0 + acol;
                if (k0 + acol + 3 < K) {
                    av = *(const float4*)src;
                } else {
                    if (k0 + acol + 0 < K) av.x = src[0];
                    if (k0 + acol + 1 < K) av.y = src[1];
                    if (k0 + acol + 2 < K) av.z = src[2];
                }
            }
        }
        As[acol + 0][arow] = av.x;
        As[acol + 1][arow] = av.y;
        As[acol + 2][arow] = av.z;
        As[acol + 3][arow] = av.w;

        // --- load W tile ---
        float4 bv = make_float4(0.f, 0.f, 0.f, 0.f);
        {
            int kk = k0 + brow;
            if (kk < K) {
                const float* src = W + (size_t)kk * N + n0 + bcol;
                if (n0 + bcol + 3 < N) {
                    bv = *(const float4*)src;
                } else {
                    if (n0 + bcol + 0 < N) bv.x = src[0];
                    if (n0 + bcol + 1 < N) bv.y = src[1];
                    if (n0 + bcol + 2 < N) bv.z = src[2];
                }
            }
        }
        *(float4*)&Bs[brow][bcol] = bv;

        __syncthreads();
#pragma unroll
        for (int k = 0; k < BK; k++) {
            float4 a = *(const float4*)&As[k][ty << 2];
            float4 b = *(const float4*)&Bs[k][tx << 2];
            acc[0][0] += a.x * b.x; acc[0][1] += a.x * b.y; acc[0][2] += a.x * b.z; acc[0][3] += a.x * b.w;
            acc[1][0] += a.y * b.x; acc[1][1] += a.y * b.y; acc[1][2] += a.y * b.z; acc[1][3] += a.y * b.w;
            acc[2][0] += a.z * b.x; acc[2][1] += a.z * b.y; acc[2][2] += a.z * b.z; acc[2][3] += a.z * b.w;
            acc[3][0] += a.w * b.x; acc[3][1] += a.w * b.y; acc[3][2] += a.w * b.z; acc[3][3] += a.w * b.w;
        }
        __syncthreads();
    }

#pragma unroll
    for (int i = 0; i < 4; i++) {
        int m = m0 + (ty << 2) + i;
        if (m >= M) continue;
#pragma unroll
        for (int j = 0; j < 4; j++) {
            int n = n0 + (tx << 2) + j;
            if (n < N) {
                float v = acc[i][j] + bias[n];
                if (relu) v = fmaxf(v, 0.f);
                C[(size_t)m * N + n] = v;
            }
        }
    }
}

// ---------------------------------------------------------------------------
// Aggregation GEMM (batched over graphs):
//   Z[g,c,f] = H[g,c,f] + sum_r A[g,r,c] * H[g,r,f]
// A operand already lives as [k=r][m=c] contiguous in m -> no transpose needed.
// ---------------------------------------------------------------------------
__global__ void __launch_bounds__(256)
agg_gemm(const float* __restrict__ H, float* __restrict__ Z, int F) {
    const int g = blockIdx.z;
    const float* Ag = g_A + (size_t)g * (NPG * NPG);
    const float* Hg = H + (size_t)g * NPG * F;

    __shared__ float As[BK][BM + 4];
    __shared__ float Bs[BK][BN + 4];

    const int tid  = threadIdx.x;
    const int m0   = blockIdx.x * BM;      // c dimension
    const int n0   = blockIdx.y * BN;      // f dimension
    const int krow = tid >> 4;             // 0..15
    const int mcol = (tid & 15) << 2;      // 0..60
    const int tx   = tid & 15;
    const int ty   = tid >> 4;

    float acc[4][4] = {};

    for (int k0 = 0; k0 < NPG; k0 += BK) {
        const int kk = k0 + krow;

        // A tile: As[k][m] = A[g][kk][m0+m]  (contiguous float4 in m)
        float4 av = make_float4(0.f, 0.f, 0.f, 0.f);
        if (kk < NPG && (m0 + mcol) < NPG) {
            av = *(const float4*)(Ag + (size_t)kk * NPG + m0 + mcol);
        }
        *(float4*)&As[krow][mcol] = av;

        // B tile: Bs[k][n] = H[g][kk][n0+n]
        float4 bv = make_float4(0.f, 0.f, 0.f, 0.f);
        if (kk < NPG) {
            const float* src = Hg + (size_t)kk * F + n0 + mcol;
            if (n0 + mcol + 3 < F) {
                bv = *(const float4*)src;
            } else {
                if (n0 + mcol + 0 < F) bv.x = src[0];
                if (n0 + mcol + 1 < F) bv.y = src[1];
                if (n0 + mcol + 2 < F) bv.z = src[2];
            }
        }
        *(float4*)&Bs[krow][mcol] = bv;

        __syncthreads();
#pragma unroll
        for (int k = 0; k < BK; k++) {
            float4 a = *(const float4*)&As[k][ty << 2];
            float4 b = *(const float4*)&Bs[k][tx << 2];
            acc[0][0] += a.x * b.x; acc[0][1] += a.x * b.y; acc[0][2] += a.x * b.z; acc[0][3] += a.x * b.w;
            acc[1][0] += a.y * b.x; acc[1][1] += a.y * b.y; acc[1][2] += a.y * b.z; acc[1][3] += a.y * b.w;
            acc[2][0] += a.z * b.x; acc[2][1] += a.z * b.y; acc[2][2] += a.z * b.z; acc[2][3] += a.z * b.w;
            acc[3][0] += a.w * b.x; acc[3][1] += a.w * b.y; acc[3][2] += a.w * b.z; acc[3][3] += a.w * b.w;
        }
        __syncthreads();
    }

#pragma unroll
    for (int i = 0; i < 4; i++) {
        int m = m0 + (ty << 2) + i;       // c index
        if (m >= NPG) continue;
#pragma unroll
        for (int j = 0; j < 4; j++) {
            int n = n0 + (tx << 2) + j;   // f index
            if (n < F) {
                Z[((size_t)g * NPG + m) * F + n] = acc[i][j] + Hg[(size_t)m * F + n];
            }
        }
    }
}

// ---------------------------------------------------------------------------
// BatchNorm: deterministic two-stage reduction (no atomics)
// ---------------------------------------------------------------------------
__global__ void __launch_bounds__(256)
bn_stats_partial(const float* __restrict__ X) {
    const int blk = blockIdx.x;     // 232 blocks, 256 rows each
    const int t   = threadIdx.x;    // 256 threads; thread owns cols t and 256+t
    float s0 = 0.f, q0 = 0.f, s1 = 0.f, q1 = 0.f;
    const int row0 = blk * 256;
    for (int r = 0; r < 256; r++) {
        const float* rowp = X + (size_t)(row0 + r) * EMB;
        float v0 = rowp[t];
        s0 += v0; q0 += v0 * v0;
        if (t < EMB - 256) {
            float v1 = rowp[256 + t];
            s1 += v1; q1 += v1 * v1;
        }
    }
    g_part[blk * 600 + t]       = s0;
    g_part[blk * 600 + 300 + t] = q0;
    if (t < EMB - 256) {
        g_part[blk * 600 + 256 + t]       = s1;
        g_part[blk * 600 + 300 + 256 + t] = q1;
    }
}

__global__ void bn_finalize(const float* __restrict__ gamma,
                            const float* __restrict__ beta) {
    int c = threadIdx.x;
    if (c >= EMB) return;
    float s = 0.f, q = 0.f;
    for (int b = 0; b < STAT_BLOCKS; b++) {
        s += g_part[b * 600 + c];
        q += g_part[b * 600 + 300 + c];
    }
    const float invN = 1.f / (float)NODES;
    float mean = s * invN;
    float var  = q * invN - mean * mean;
    float sc   = gamma[c] * rsqrtf(var + BN_EPS);
    g_ss[c]       = sc;
    g_ss[300 + c] = beta[c] - mean * sc;
}

__global__ void __launch_bounds__(256)
bn_apply(float* __restrict__ X, float* __restrict__ out2, int relu, size_t n) {
    size_t i = (size_t)blockIdx.x * blockDim.x + threadIdx.x;
    if (i >= n) return;
    int c = (int)(i % EMB);
    float v = X[i] * g_ss[c] + g_ss[300 + c];
    if (relu) v = fmaxf(v, 0.f);
    X[i] = v;
    if (out2) out2[i] = v;
}

// ---------------------------------------------------------------------------
// Graph pooling: segment sum over the 116 contiguous nodes of each graph
// ---------------------------------------------------------------------------
__global__ void xpool_kernel(const float* __restrict__ H, float* __restrict__ out) {
    int g = blockIdx.x;
    int c = threadIdx.x;
    if (c >= EMB) return;
    const float* base = H + (size_t)g * NPG * EMB + c;
    float s = 0.f;
    for (int r = 0; r < NPG; r++) s += base[(size_t)r * EMB];
    out[(size_t)g * EMB + c] = s;
}

// ---------------------------------------------------------------------------
// Launch
// ---------------------------------------------------------------------------
extern "C" void kernel_launch(void* const* d_in, const int* in_sizes, int n_in,
                              void* d_out, int out_size) {
    const float* x           = (const float*)d_in[1];
    const int*   edge_index  = (const int*)d_in[2];
    const float* edge_weight = (const float*)d_in[4];
    const float* baw         = (const float*)d_in[5];
    const float* W1_0   = (const float*)d_in[6];
    const float* b1_0   = (const float*)d_in[7];
    const float* W2_0   = (const float*)d_in[8];
    const float* b2_0   = (const float*)d_in[9];
    const float* W1s    = (const float*)d_in[10];
    const float* b1s    = (const float*)d_in[11];
    const float* W2s    = (const float*)d_in[12];
    const float* b2s    = (const float*)d_in[13];
    const float* gammas = (const float*)d_in[14];
    const float* betas  = (const float*)d_in[15];
    const int E = in_sizes[4];

    float *A_, *Z_, *T_, *H_;
    cudaGetSymbolAddress((void**)&A_, g_A);
    cudaGetSymbolAddress((void**)&Z_, g_Z);
    cudaGetSymbolAddress((void**)&T_, g_T);
    cudaGetSymbolAddress((void**)&H_, g_H);

    float* out       = (float*)d_out;
    float* out_xpool = out;                      // [512, 300]
    float* out_xout  = out + (size_t)NG * EMB;   // [59392, 300]

    // Adjacency: zero then direct scatter (edge positions are unique)
    {
        int n4 = ADJ_ELEMS / 4;
        zero4_kernel<<<(n4 + 255) / 256, 256>>>((float4*)A_, n4);
        build_adj_kernel<<<(E + 255) / 256, 256>>>(edge_index, edge_weight,
                                                   baw + 2 * (size_t)E, E);
    }

    const float* H = x;   // layer-0 input, F = 116
    for (int i = 0; i < NLAYER; i++) {
        const int F = (i == 0) ? NPG : EMB;
        const float* W1 = (i == 0) ? W1_0 : W1s + (size_t)(i - 1) * EMB * EMB;
        const float* b1 = (i == 0) ? b1_0 : b1s + (size_t)(i - 1) * EMB;
        const float* W2 = (i == 0) ? W2_0 : W2s + (size_t)(i - 1) * EMB * EMB;
        const float* b2 = (i == 0) ? b2_0 : b2s + (size_t)(i - 1) * EMB;

        // Z = H + A^T H
        dim3 gagg((NPG + BM - 1) / BM, (F + BN - 1) / BN, NG);
        agg_gemm<<<gagg, 256>>>(H, Z_, F);

        // T = relu(Z @ W1 + b1)
        dim3 g1((NODES + BM - 1) / BM, (EMB + BN - 1) / BN);
        gemm_bias_act<<<g1, 256>>>(Z_, W1, b1, T_, NODES, F, EMB, 1);

        // H_ = T @ W2 + b2   (pre-BN; overwrites previous H which is consumed)
        gemm_bias_act<<<g1, 256>>>(T_, W2, b2, H_, NODES, EMB, EMB, 0);

        // BatchNorm (+ relu except last layer)
        bn_stats_partial<<<STAT_BLOCKS, 256>>>(H_);
        bn_finalize<<<1, EMB>>>(gammas + i * EMB, betas + i * EMB);
        size_t n = (size_t)NODES * EMB;
        bn_apply<<<(unsigned)((n + 255) / 256), 256>>>(
            H_, (i == NLAYER - 1) ? out_xout : nullptr, (i < NLAYER - 1) ? 1 : 0, n);

        H = H_;
    }

    // xpool = per-graph sum of final node features
    xpool_kernel<<<NG, 320>>>(H_, out_xpool);
}

// round 3
// speedup vs baseline: 1.0007x; 1.0007x over previous
#include <cuda_runtime.h>
#include <cstdint>

// ---------------------------------------------------------------------------
// Problem constants
// ---------------------------------------------------------------------------
#define NG    512           // graphs
#define NPG   116           // nodes per graph
#define EMB   300
#define NODES (NG * NPG)    // 59392
#define ADJ_ELEMS (NG * NPG * NPG)   // 6,889,472
#define NLAYER 5
#define BN_EPS 1e-5f

#define STAT_BLOCKS 232     // 232 * 256 = 59392 rows exactly

// GEMM tiling
#define BM 64
#define BN 64
#define BK 16

// ---------------------------------------------------------------------------
// Device scratch (static allocation only; no cudaMalloc allowed)
// ---------------------------------------------------------------------------
__device__ float g_A[ADJ_ELEMS];                 // dense adjacency  [G][116][116]
__device__ float g_Z[(size_t)NODES * EMB];       // post-aggregation
__device__ float g_T[(size_t)NODES * EMB];       // hidden (after relu(W1))
__device__ float g_H[(size_t)NODES * EMB];       // layer output / BN in-place
__device__ float g_part[STAT_BLOCKS * 600];      // BN partial sums  [blk][sum300|sq300]
__device__ float g_ss[600];                      // BN scale[300], shift[300]

// ---------------------------------------------------------------------------
// Adjacency construction
// ---------------------------------------------------------------------------
__global__ void zero4_kernel(float4* __restrict__ p, int n4) {
    int i = blockIdx.x * blockDim.x + threadIdx.x;
    if (i < n4) p[i] = make_float4(0.f, 0.f, 0.f, 0.f);
}

__global__ void build_adj_kernel(const int* __restrict__ ei,
                                 const float* __restrict__ ew,
                                 const float* __restrict__ bern,
                                 int E) {
    int e = blockIdx.x * blockDim.x + threadIdx.x;
    if (e >= E) return;
    int r = ei[e];
    int c = ei[E + e];
    int g = r / NPG;
    float w = ew[e] * bern[e];
    g_A[(size_t)g * (NPG * NPG) + (r - g * NPG) * NPG + (c - g * NPG)] = w;
}

// ---------------------------------------------------------------------------
// MLP GEMM:  C[M,N] = act( X[M,K] @ W[K,N] + bias[N] )
// 64x64x16 tiles, 4x4 register microtile, 256 threads
// ---------------------------------------------------------------------------
__global__ void __launch_bounds__(256)
gemm_bias_act(const float* __restrict__ X, const float* __restrict__ W,
              const float* __restrict__ bias, float* __restrict__ C,
              int M, int K, int N, int relu) {
    __shared__ float As[BK][BM + 4];   // transposed: As[k][m]
    __shared__ float Bs[BK][BN + 4];

    const int tid  = threadIdx.x;
    const int m0   = blockIdx.x * BM;
    const int n0   = blockIdx.y * BN;
    const int arow = tid >> 2;             // 0..63 (m within tile)
    const int acol = (tid & 3) << 2;       // 0,4,8,12 (k within tile)
    const int brow = tid >> 4;             // 0..15 (k within tile)
    const int bcol = (tid & 15) << 2;      // 0..60 (n within tile)
    const int tx   = tid & 15;
    const int ty   = tid >> 4;

    float acc[4][4] = {};

    for (int k0 = 0; k0 < K; k0 += BK) {
        // --- load X tile (transposed into As) ---
        float4 av = make_float4(0.f, 0.f, 0.f, 0.f);
        {
            int m = m0 + arow;
            if (m < M) {
                const float* src = X + (size_t)m * K + k0 + acol;
                if (k0 + acol + 3 < K) {
                    av = *(const float4*)src;
                } else {
                    if (k0 + acol + 0 < K) av.x = src[0];
                    if (k0 + acol + 1 < K) av.y = src[1];
                    if (k0 + acol + 2 < K) av.z = src[2];
                }
            }
        }
        As[acol + 0][arow] = av.x;
        As[acol + 1][arow] = av.y;
        As[acol + 2][arow] = av.z;
        As[acol + 3][arow] = av.w;

        // --- load W tile ---
        float4 bv = make_float4(0.f, 0.f, 0.f, 0.f);
        {
            int kk = k0 + brow;
            if (kk < K) {
                const float* src = W + (size_t)kk * N + n0 + bcol;
                if (n0 + bcol + 3 < N) {
                    bv = *(const float4*)src;
                } else {
                    if (n0 + bcol + 0 < N) bv.x = src[0];
                    if (n0 + bcol + 1 < N) bv.y = src[1];
                    if (n0 + bcol + 2 < N) bv.z = src[2];
                }
            }
        }
        *(float4*)&Bs[brow][bcol] = bv;

        __syncthreads();
#pragma unroll
        for (int k = 0; k < BK; k++) {
            float4 a = *(const float4*)&As[k][ty << 2];
            float4 b = *(const float4*)&Bs[k][tx << 2];
            acc[0][0] += a.x * b.x; acc[0][1] += a.x * b.y; acc[0][2] += a.x * b.z; acc[0][3] += a.x * b.w;
            acc[1][0] += a.y * b.x; acc[1][1] += a.y * b.y; acc[1][2] += a.y * b.z; acc[1][3] += a.y * b.w;
            acc[2][0] += a.z * b.x; acc[2][1] += a.z * b.y; acc[2][2] += a.z * b.z; acc[2][3] += a.z * b.w;
            acc[3][0] += a.w * b.x; acc[3][1] += a.w * b.y; acc[3][2] += a.w * b.z; acc[3][3] += a.w * b.w;
        }
        __syncthreads();
    }

#pragma unroll
    for (int i = 0; i < 4; i++) {
        int m = m0 + (ty << 2) + i;
        if (m >= M) continue;
#pragma unroll
        for (int j = 0; j < 4; j++) {
            int n = n0 + (tx << 2) + j;
            if (n < N) {
                float v = acc[i][j] + bias[n];
                if (relu) v = fmaxf(v, 0.f);
                C[(size_t)m * N + n] = v;
            }
        }
    }
}

// ---------------------------------------------------------------------------
// Aggregation GEMM (batched over graphs):
//   Z[g,c,f] = H[g,c,f] + sum_r A[g,r,c] * H[g,r,f]
// A operand already lives as [k=r][m=c] contiguous in m -> no transpose needed.
// ---------------------------------------------------------------------------
__global__ void __launch_bounds__(256)
agg_gemm(const float* __restrict__ H, float* __restrict__ Z, int F) {
    const int g = blockIdx.z;
    const float* Ag = g_A + (size_t)g * (NPG * NPG);
    const float* Hg = H + (size_t)g * NPG * F;

    __shared__ float As[BK][BM + 4];
    __shared__ float Bs[BK][BN + 4];

    const int tid  = threadIdx.x;
    const int m0   = blockIdx.x * BM;      // c dimension
    const int n0   = blockIdx.y * BN;      // f dimension
    const int krow = tid >> 4;             // 0..15
    const int mcol = (tid & 15) << 2;      // 0..60
    const int tx   = tid & 15;
    const int ty   = tid >> 4;

    float acc[4][4] = {};

    for (int k0 = 0; k0 < NPG; k0 += BK) {
        const int kk = k0 + krow;

        // A tile: As[k][m] = A[g][kk][m0+m]  (contiguous float4 in m)
        float4 av = make_float4(0.f, 0.f, 0.f, 0.f);
        if (kk < NPG && (m0 + mcol) < NPG) {
            av = *(const float4*)(Ag + (size_t)kk * NPG + m0 + mcol);
        }
        *(float4*)&As[krow][mcol] = av;

        // B tile: Bs[k][n] = H[g][kk][n0+n]
        float4 bv = make_float4(0.f, 0.f, 0.f, 0.f);
        if (kk < NPG) {
            const float* src = Hg + (size_t)kk * F + n0 + mcol;
            if (n0 + mcol + 3 < F) {
                bv = *(const float4*)src;
            } else {
                if (n0 + mcol + 0 < F) bv.x = src[0];
                if (n0 + mcol + 1 < F) bv.y = src[1];
                if (n0 + mcol + 2 < F) bv.z = src[2];
            }
        }
        *(float4*)&Bs[krow][mcol] = bv;

        __syncthreads();
#pragma unroll
        for (int k = 0; k < BK; k++) {
            float4 a = *(const float4*)&As[k][ty << 2];
            float4 b = *(const float4*)&Bs[k][tx << 2];
            acc[0][0] += a.x * b.x; acc[0][1] += a.x * b.y; acc[0][2] += a.x * b.z; acc[0][3] += a.x * b.w;
            acc[1][0] += a.y * b.x; acc[1][1] += a.y * b.y; acc[1][2] += a.y * b.z; acc[1][3] += a.y * b.w;
            acc[2][0] += a.z * b.x; acc[2][1] += a.z * b.y; acc[2][2] += a.z * b.z; acc[2][3] += a.z * b.w;
            acc[3][0] += a.w * b.x; acc[3][1] += a.w * b.y; acc[3][2] += a.w * b.z; acc[3][3] += a.w * b.w;
        }
        __syncthreads();
    }

#pragma unroll
    for (int i = 0; i < 4; i++) {
        int m = m0 + (ty << 2) + i;       // c index
        if (m >= NPG) continue;
#pragma unroll
        for (int j = 0; j < 4; j++) {
            int n = n0 + (tx << 2) + j;   // f index
            if (n < F) {
                Z[((size_t)g * NPG + m) * F + n] = acc[i][j] + Hg[(size_t)m * F + n];
            }
        }
    }
}

// ---------------------------------------------------------------------------
// BatchNorm: deterministic two-stage reduction (no atomics)
// ---------------------------------------------------------------------------
__global__ void __launch_bounds__(256)
bn_stats_partial(const float* __restrict__ X) {
    const int blk = blockIdx.x;     // 232 blocks, 256 rows each
    const int t   = threadIdx.x;    // 256 threads; thread owns cols t and 256+t
    float s0 = 0.f, q0 = 0.f, s1 = 0.f, q1 = 0.f;
    const int row0 = blk * 256;
    for (int r = 0; r < 256; r++) {
        const float* rowp = X + (size_t)(row0 + r) * EMB;
        float v0 = rowp[t];
        s0 += v0; q0 += v0 * v0;
        if (t < EMB - 256) {
            float v1 = rowp[256 + t];
            s1 += v1; q1 += v1 * v1;
        }
    }
    g_part[blk * 600 + t]       = s0;
    g_part[blk * 600 + 300 + t] = q0;
    if (t < EMB - 256) {
        g_part[blk * 600 + 256 + t]       = s1;
        g_part[blk * 600 + 300 + 256 + t] = q1;
    }
}

__global__ void bn_finalize(const float* __restrict__ gamma,
                            const float* __restrict__ beta) {
    int c = threadIdx.x;
    if (c >= EMB) return;
    float s = 0.f, q = 0.f;
    for (int b = 0; b < STAT_BLOCKS; b++) {
        s += g_part[b * 600 + c];
        q += g_part[b * 600 + 300 + c];
    }
    const float invN = 1.f / (float)NODES;
    float mean = s * invN;
    float var  = q * invN - mean * mean;
    float sc   = gamma[c] * rsqrtf(var + BN_EPS);
    g_ss[c]       = sc;
    g_ss[300 + c] = beta[c] - mean * sc;
}

__global__ void __launch_bounds__(256)
bn_apply(float* __restrict__ X, float* __restrict__ out2, int relu, size_t n) {
    size_t i = (size_t)blockIdx.x * blockDim.x + threadIdx.x;
    if (i >= n) return;
    int c = (int)(i % EMB);
    float v = X[i] * g_ss[c] + g_ss[300 + c];
    if (relu) v = fmaxf(v, 0.f);
    X[i] = v;
    if (out2) out2[i] = v;
}

// ---------------------------------------------------------------------------
// Graph pooling: segment sum over the 116 contiguous nodes of each graph
// ---------------------------------------------------------------------------
__global__ void xpool_kernel(const float* __restrict__ H, float* __restrict__ out) {
    int g = blockIdx.x;
    int c = threadIdx.x;
    if (c >= EMB) return;
    const float* base = H + (size_t)g * NPG * EMB + c;
    float s = 0.f;
    for (int r = 0; r < NPG; r++) s += base[(size_t)r * EMB];
    out[(size_t)g * EMB + c] = s;
}

// ---------------------------------------------------------------------------
// Launch
// ---------------------------------------------------------------------------
extern "C" void kernel_launch(void* const* d_in, const int* in_sizes, int n_in,
                              void* d_out, int out_size) {
    const float* x           = (const float*)d_in[1];
    const int*   edge_index  = (const int*)d_in[2];
    const float* edge_weight = (const float*)d_in[4];
    const float* baw         = (const float*)d_in[5];
    const float* W1_0   = (const float*)d_in[6];
    const float* b1_0   = (const float*)d_in[7];
    const float* W2_0   = (const float*)d_in[8];
    const float* b2_0   = (const float*)d_in[9];
    const float* W1s    = (const float*)d_in[10];
    const float* b1s    = (const float*)d_in[11];
    const float* W2s    = (const float*)d_in[12];
    const float* b2s    = (const float*)d_in[13];
    const float* gammas = (const float*)d_in[14];
    const float* betas  = (const float*)d_in[15];
    const int E = in_sizes[4];

    float *A_, *Z_, *T_, *H_;
    cudaGetSymbolAddress((void**)&A_, g_A);
    cudaGetSymbolAddress((void**)&Z_, g_Z);
    cudaGetSymbolAddress((void**)&T_, g_T);
    cudaGetSymbolAddress((void**)&H_, g_H);

    float* out       = (float*)d_out;
    float* out_xpool = out;                      // [512, 300]
    float* out_xout  = out + (size_t)NG * EMB;   // [59392, 300]

    // Adjacency: zero then direct scatter (edge positions are unique)
    {
        int n4 = ADJ_ELEMS / 4;
        zero4_kernel<<<(n4 + 255) / 256, 256>>>((float4*)A_, n4);
        build_adj_kernel<<<(E + 255) / 256, 256>>>(edge_index, edge_weight,
                                                   baw + 2 * (size_t)E, E);
    }

    const float* H = x;   // layer-0 input, F = 116
    for (int i = 0; i < NLAYER; i++) {
        const int F = (i == 0) ? NPG : EMB;
        const float* W1 = (i == 0) ? W1_0 : W1s + (size_t)(i - 1) * EMB * EMB;
        const float* b1 = (i == 0) ? b1_0 : b1s + (size_t)(i - 1) * EMB;
        const float* W2 = (i == 0) ? W2_0 : W2s + (size_t)(i - 1) * EMB * EMB;
        const float* b2 = (i == 0) ? b2_0 : b2s + (size_t)(i - 1) * EMB;

        // Z = H + A^T H
        dim3 gagg((NPG + BM - 1) / BM, (F + BN - 1) / BN, NG);
        agg_gemm<<<gagg, 256>>>(H, Z_, F);

        // T = relu(Z @ W1 + b1)
        dim3 g1((NODES + BM - 1) / BM, (EMB + BN - 1) / BN);
        gemm_bias_act<<<g1, 256>>>(Z_, W1, b1, T_, NODES, F, EMB, 1);

        // H_ = T @ W2 + b2   (pre-BN; overwrites previous H which is consumed)
        gemm_bias_act<<<g1, 256>>>(T_, W2, b2, H_, NODES, EMB, EMB, 0);

        // BatchNorm (+ relu except last layer)
        bn_stats_partial<<<STAT_BLOCKS, 256>>>(H_);
        bn_finalize<<<1, EMB>>>(gammas + i * EMB, betas + i * EMB);
        size_t n = (size_t)NODES * EMB;
        bn_apply<<<(unsigned)((n + 255) / 256), 256>>>(
            H_, (i == NLAYER - 1) ? out_xout : nullptr, (i < NLAYER - 1) ? 1 : 0, n);

        H = H_;
    }

    // xpool = per-graph sum of final node features
    xpool_kernel<<<NG, 320>>>(H_, out_xpool);
}